// round 1
// baseline (speedup 1.0000x reference)
#include <cuda_runtime.h>

// Conv2d 3x3 VALID, C_in=C_out=8, 2048x2048 fp32 -> (8, 2046, 2046)
// Strategy: packed fp32x2 FMA (fma.rn.f32x2) direct convolution.
// Each thread: 2 output rows x 4 output cols x 8 cout = 64 outputs,
// held as 32 packed f32x2 accumulators.

#define CIN  8
#define COUT 8
#define IH   2048
#define IW   2048
#define OHH  2046
#define OWW  2046
#define ROWS 2
#define PX   4

typedef unsigned long long ull;

__device__ __forceinline__ ull pack2(float lo, float hi) {
    ull r;
    asm("mov.b64 %0, {%1, %2};"
        : "=l"(r)
        : "r"(__float_as_uint(lo)), "r"(__float_as_uint(hi)));
    return r;
}

__device__ __forceinline__ ull fma2(ull a, ull b, ull c) {
    ull d;
    asm("fma.rn.f32x2 %0, %1, %2, %3;"
        : "=l"(d)
        : "l"(a), "l"(b), "l"(c));
    return d;
}

__global__ __launch_bounds__(128)
void conv3x3_f32x2_kernel(const float* __restrict__ x,
                          const float* __restrict__ w,
                          float* __restrict__ out) {
    // Packed (w, w) weights in shared: layout [cin][ky][kx][cout]
    __shared__ ull wsh[CIN * 3 * 3 * COUT];

    const int tid = threadIdx.y * blockDim.x + threadIdx.x;
    for (int i = tid; i < CIN * 9 * COUT; i += 128) {
        int cout = i & 7;
        int rest = i >> 3;          // 0..71
        int kx   = rest % 3;
        int ky   = (rest / 3) % 3;
        int cin  = rest / 9;
        float wv = w[((cout * CIN + cin) * 3 + ky) * 3 + kx];
        wsh[i] = pack2(wv, wv);
    }
    __syncthreads();

    const int tile_x = blockIdx.x * 32 + threadIdx.x;   // 0..511
    const int tile_y = blockIdx.y * 4  + threadIdx.y;   // 0..1023 (1023 invalid)
    if (tile_y * ROWS >= OHH) return;

    int x0 = tile_x * PX;
    if (x0 > OWW - PX) x0 = OWW - PX;   // clamp tail: overlapping identical writes
    const int y0 = tile_y * ROWS;

    ull acc[COUT][ROWS][PX / 2];
    #pragma unroll
    for (int co = 0; co < COUT; ++co)
        #pragma unroll
        for (int r = 0; r < ROWS; ++r)
            #pragma unroll
            for (int p = 0; p < PX / 2; ++p)
                acc[co][r][p] = 0ull;

    #pragma unroll 1
    for (int cin = 0; cin < CIN; ++cin) {
        const float* ip = x + (size_t)cin * (IH * IW) + (size_t)y0 * IW + x0;

        // Input rows y0..y0+3, cols x0..x0+5, packed as overlapping pairs
        ull P[ROWS + 2][PX + 1];
        #pragma unroll
        for (int r = 0; r < ROWS + 2; ++r) {
            float v0 = __ldg(ip + r * IW + 0);
            float v1 = __ldg(ip + r * IW + 1);
            float v2 = __ldg(ip + r * IW + 2);
            float v3 = __ldg(ip + r * IW + 3);
            float v4 = __ldg(ip + r * IW + 4);
            float v5 = __ldg(ip + r * IW + 5);
            P[r][0] = pack2(v0, v1);
            P[r][1] = pack2(v1, v2);
            P[r][2] = pack2(v2, v3);
            P[r][3] = pack2(v3, v4);
            P[r][4] = pack2(v4, v5);
        }

        #pragma unroll
        for (int ky = 0; ky < 3; ++ky) {
            #pragma unroll
            for (int co = 0; co < COUT; ++co) {
                #pragma unroll
                for (int kx = 0; kx < 3; ++kx) {
                    ull w2 = wsh[((cin * 3 + ky) * 3 + kx) * COUT + co];
                    #pragma unroll
                    for (int r = 0; r < ROWS; ++r) {
                        acc[co][r][0] = fma2(P[r + ky][kx],     w2, acc[co][r][0]);
                        acc[co][r][1] = fma2(P[r + ky][kx + 2], w2, acc[co][r][1]);
                    }
                }
            }
        }
    }

    // Store: each acc is a (x, x+1) pair -> 8B-aligned float2 store
    #pragma unroll
    for (int co = 0; co < COUT; ++co) {
        #pragma unroll
        for (int r = 0; r < ROWS; ++r) {
            float* op = out + (size_t)co * (OHH * OWW) + (size_t)(y0 + r) * OWW + x0;
            #pragma unroll
            for (int p = 0; p < PX / 2; ++p) {
                union { ull u; float2 f; } cv;
                cv.u = acc[co][r][p];
                *reinterpret_cast<float2*>(op + 2 * p) = cv.f;
            }
        }
    }
}

extern "C" void kernel_launch(void* const* d_in, const int* in_sizes, int n_in,
                              void* d_out, int out_size) {
    const float* x = (const float*)d_in[0];   // (8, 2048, 2048) fp32
    const float* w = (const float*)d_in[1];   // (8, 8, 3, 3) fp32
    float* out = (float*)d_out;               // (8, 2046, 2046) fp32

    // tiles_x = ceil(2046/4) = 512 -> grid.x = 512/32 = 16
    // tiles_y = 2046/2 = 1023     -> grid.y = ceil(1023/4) = 256
    dim3 block(32, 4);
    dim3 grid(16, 256);
    conv3x3_f32x2_kernel<<<grid, block>>>(x, w, out);
}

// round 2
// speedup vs baseline: 1.0665x; 1.0665x over previous
#include <cuda_runtime.h>

// Conv2d 3x3 VALID, C_in=C_out=8, 2048x2048 fp32 -> (8, 2046, 2046)
// Round 2: packed fp32x2 FMA + vectorized (float4/float2) loads +
// explicit cin software pipeline + paired LDS.128 weight loads.

#define CIN  8
#define COUT 8
#define IH   2048
#define IW   2048
#define OHH  2046
#define OWW  2046
#define CH   (IH * IW)

typedef unsigned long long ull;

__device__ __forceinline__ ull pack2(float lo, float hi) {
    ull r;
    asm("mov.b64 %0, {%1, %2};"
        : "=l"(r)
        : "r"(__float_as_uint(lo)), "r"(__float_as_uint(hi)));
    return r;
}

__device__ __forceinline__ ull fma2(ull a, ull b, ull c) {
    ull d;
    asm("fma.rn.f32x2 %0, %1, %2, %3;"
        : "=l"(d)
        : "l"(a), "l"(b), "l"(c));
    return d;
}

__global__ __launch_bounds__(128)
void conv3x3_f32x2_kernel(const float* __restrict__ x,
                          const float* __restrict__ w,
                          float* __restrict__ out) {
    // Packed (w, w) weights in shared: layout [cin][ky][kx][cout]
    __shared__ ull wsh[CIN * 9 * COUT];

    const int tid = threadIdx.y * 32 + threadIdx.x;
    for (int i = tid; i < CIN * 9 * COUT; i += 128) {
        int co   = i & 7;
        int rest = i >> 3;
        int kx   = rest % 3;
        int ky   = (rest / 3) % 3;
        int cin  = rest / 9;
        float wv = w[((co * CIN + cin) * 3 + ky) * 3 + kx];
        wsh[i] = pack2(wv, wv);
    }
    __syncthreads();

    const int tile_x = blockIdx.x * 32 + threadIdx.x;   // 0..511
    const int tile_y = blockIdx.y * 4  + threadIdx.y;
    const int y0 = tile_y * 2;
    if (y0 >= OHH) return;

    const int x0 = tile_x * 4;                 // 0..2044, always 16B aligned
    const bool edge = (x0 >= OWW - 2);         // x0 == 2044: cols 2046/2047 are garbage
    const int boff = edge ? 2 : 4;             // edge: in-bounds dummy float2

    const float* ip = x + (size_t)y0 * IW + x0;

    // Current-cin raw inputs (4 rows x 6 floats; edge: last 2 are dummies)
    float4 A[4];
    float2 B[4];
    #pragma unroll
    for (int r = 0; r < 4; ++r) {
        A[r] = *reinterpret_cast<const float4*>(ip + r * IW);
        B[r] = *reinterpret_cast<const float2*>(ip + r * IW + boff);
    }

    ull acc[COUT][2][2];
    #pragma unroll
    for (int co = 0; co < COUT; ++co)
        #pragma unroll
        for (int r = 0; r < 2; ++r) {
            acc[co][r][0] = 0ull;
            acc[co][r][1] = 0ull;
        }

    #pragma unroll
    for (int cin = 0; cin < CIN; ++cin) {
        // Build overlapping packed pairs for 4 input rows
        ull P[4][5];
        #pragma unroll
        for (int r = 0; r < 4; ++r) {
            P[r][0] = pack2(A[r].x, A[r].y);
            P[r][1] = pack2(A[r].y, A[r].z);
            P[r][2] = pack2(A[r].z, A[r].w);
            P[r][3] = pack2(A[r].w, B[r].x);
            P[r][4] = pack2(B[r].x, B[r].y);
        }

        // Prefetch next cin's inputs; the FMA block below hides the latency
        if (cin + 1 < CIN) {
            const float* np = ip + (size_t)(cin + 1) * CH;
            #pragma unroll
            for (int r = 0; r < 4; ++r) {
                A[r] = *reinterpret_cast<const float4*>(np + r * IW);
                B[r] = *reinterpret_cast<const float2*>(np + r * IW + boff);
            }
        }

        const ull* wp = &wsh[cin * 9 * COUT];
        #pragma unroll
        for (int ky = 0; ky < 3; ++ky) {
            #pragma unroll
            for (int kx = 0; kx < 3; ++kx) {
                #pragma unroll
                for (int cp = 0; cp < 4; ++cp) {
                    ulonglong2 w2 = *reinterpret_cast<const ulonglong2*>(
                        &wp[(ky * 3 + kx) * COUT + cp * 2]);
                    #pragma unroll
                    for (int r = 0; r < 2; ++r) {
                        acc[cp*2  ][r][0] = fma2(P[r+ky][kx  ], w2.x, acc[cp*2  ][r][0]);
                        acc[cp*2  ][r][1] = fma2(P[r+ky][kx+2], w2.x, acc[cp*2  ][r][1]);
                        acc[cp*2+1][r][0] = fma2(P[r+ky][kx  ], w2.y, acc[cp*2+1][r][0]);
                        acc[cp*2+1][r][1] = fma2(P[r+ky][kx+2], w2.y, acc[cp*2+1][r][1]);
                    }
                }
            }
        }
    }

    // Store packed pairs; edge tile stores only its first pair (cols 2044/2045)
    #pragma unroll
    for (int co = 0; co < COUT; ++co) {
        #pragma unroll
        for (int r = 0; r < 2; ++r) {
            float* op = out + (size_t)co * (OHH * OWW) + (size_t)(y0 + r) * OWW + x0;
            union { ull u; float2 f; } c0, c1;
            c0.u = acc[co][r][0];
            *reinterpret_cast<float2*>(op) = c0.f;
            if (!edge) {
                c1.u = acc[co][r][1];
                *reinterpret_cast<float2*>(op + 2) = c1.f;
            }
        }
    }
}

extern "C" void kernel_launch(void* const* d_in, const int* in_sizes, int n_in,
                              void* d_out, int out_size) {
    const float* x = (const float*)d_in[0];   // (8, 2048, 2048) fp32
    const float* w = (const float*)d_in[1];   // (8, 8, 3, 3) fp32
    float* out = (float*)d_out;               // (8, 2046, 2046) fp32

    dim3 block(32, 4);
    dim3 grid(16, 256);                        // 512 x-tiles, 1024 y-tiles (1 masked)
    conv3x3_f32x2_kernel<<<grid, block>>>(x, w, out);
}